// round 11
// baseline (speedup 1.0000x reference)
#include <cuda_runtime.h>
#include <cstdint>

// DepenL: out1[m] = Uk[m]*Uq[mc], out2[m] = Uk[mc]*Uq[m], mc = 9*(m/9)+4.
// m = p*L + l, U[m] = x[l/128 + p/3 - 1, l%128 + p%3 - 1] (0 outside).
// L mod 9 == 4 => center = same-plane pixel l + d, d = 4 - (m mod 9) in [-4,4].
// 4-wide vectorized; HC=8 tiles (4096 CTAs); occupancy forced to 6 CTAs/SM.

#define WW   128
#define LL   16384
#define MM   147456
#define HC   8
#define NR   12        // HC + 2*2 halo rows
#define RS   136       // row stride floats (16B-aligned rows)
#define NT   256
#define SMN  (NR * RS)

__device__ __noinline__ float2 slow_center(const float* __restrict__ kb,
                                           const float* __restrict__ qb, int m) {
    const int g  = m / 9;
    const int mc = g * 9 + 4;
    const int pc = mc >> 14;
    const int lc = mc & 16383;
    const int ic = (pc * 11) >> 5;
    const int jc = pc - ic * 3;
    const int h  = (lc >> 7) + ic - 1;
    const int w  = (lc & 127) + jc - 1;
    if (((unsigned)h < 128u) && ((unsigned)w < 128u)) {
        const int gi = (h << 7) + w;
        return make_float2(__ldg(kb + gi), __ldg(qb + gi));
    }
    return make_float2(0.f, 0.f);
}

__global__ __launch_bounds__(NT, 6)
void depenl_v4(const float* __restrict__ key, const float* __restrict__ query,
               float* __restrict__ out1, float* __restrict__ out2) {
    __shared__ float sK[SMN];
    __shared__ float sQ[SMN];

    const int bx    = blockIdx.x;
    const int ch    = bx >> 4;         // 0..255
    const int chunk = bx & 15;         // 0..15
    const int h0    = chunk * HC;
    const int l0    = h0 * WW;
    const int tid   = threadIdx.x;
    const int tid4  = tid * 4;

    const float* __restrict__ kb = key   + (size_t)ch * LL;
    const float* __restrict__ qb = query + (size_t)ch * LL;

    for (int idx = tid; idx < SMN; idx += NT) { sK[idx] = 0.f; sQ[idx] = 0.f; }
    __syncthreads();
    for (int t = tid; t < NR * 32; t += NT) {
        const int r = t >> 5, c4 = (t & 31) * 4;
        const int gh = h0 - 2 + r;
        if ((unsigned)gh < 128u) {
            *reinterpret_cast<float4*>(&sK[r * RS + 4 + c4]) =
                *reinterpret_cast<const float4*>(kb + gh * WW + c4);
            *reinterpret_cast<float4*>(&sQ[r * RS + 4 + c4]) =
                *reinterpret_cast<const float4*>(qb + gh * WW + c4);
        }
    }
    __syncthreads();

    float* const o1c = out1 + (size_t)ch * MM + l0 + tid4;
    float* const o2c = out2 + (size_t)ch * MM + l0 + tid4;

    const int nb0 = ((tid4 >> 7) + 1) * RS + (tid4 & 127) + 4;  // i=0 quad base

    int rp = (l0 + tid4) % 9;          // m mod 9 at p=0

    #pragma unroll
    for (int p = 0; p < 9; ++p) {
        const int i = (p * 11) >> 5;   // p/3  (compile-time after unroll)
        const int j = p - i * 3;       // p%3

        // neighbor window [w+j-1 .. w+j+2] from aligned quads at col w+4
        const int abase = nb0 + i * RS;
        const float4 bk = *reinterpret_cast<const float4*>(&sK[abase]);
        const float4 bq = *reinterpret_cast<const float4*>(&sQ[abase]);
        float wk0, wk1, wk2, wk3, wq0, wq1, wq2, wq3;
        if (j == 0) {
            const float4 ak = *reinterpret_cast<const float4*>(&sK[abase - 4]);
            const float4 aq = *reinterpret_cast<const float4*>(&sQ[abase - 4]);
            wk0 = ak.w; wk1 = bk.x; wk2 = bk.y; wk3 = bk.z;
            wq0 = aq.w; wq1 = bq.x; wq2 = bq.y; wq3 = bq.z;
        } else if (j == 1) {
            wk0 = bk.x; wk1 = bk.y; wk2 = bk.z; wk3 = bk.w;
            wq0 = bq.x; wq1 = bq.y; wq2 = bq.z; wq3 = bq.w;
        } else {
            const float4 ck = *reinterpret_cast<const float4*>(&sK[abase + 4]);
            const float4 cq = *reinterpret_cast<const float4*>(&sQ[abase + 4]);
            wk0 = bk.y; wk1 = bk.z; wk2 = bk.w; wk3 = ck.x;
            wq0 = bq.y; wq1 = bq.z; wq2 = bq.w; wq3 = cq.x;
        }

        const int d0  = 4 - rp;
        const int lcl = tid4 + d0;
        const int glc = l0 + lcl;
        float4 r1, r2;
        if ((unsigned)glc <= (unsigned)(LL - 10)) {
            const int c0  = ((lcl >> 7) + i + 1) * RS + (lcl & 127) + (j + 3);
            const int l1v = lcl + 9;
            const int c1  = ((l1v >> 7) + i + 1) * RS + (l1v & 127) + (j + 3);
            const float kc0 = sK[c0], qc0 = sQ[c0];
            const float kc1 = sK[c1], qc1 = sQ[c1];
            const float kA = kc0,                  qA = qc0;
            const float kB = (rp < 8) ? kc0 : kc1, qB = (rp < 8) ? qc0 : qc1;
            const float kC = (rp < 7) ? kc0 : kc1, qC = (rp < 7) ? qc0 : qc1;
            const float kD = (rp < 6) ? kc0 : kc1, qD = (rp < 6) ? qc0 : qc1;
            r1.x = wk0 * qA;  r2.x = kA * wq0;
            r1.y = wk1 * qB;  r2.y = kB * wq1;
            r1.z = wk2 * qC;  r2.z = kC * wq2;
            r1.w = wk3 * qD;  r2.w = kD * wq3;
        } else {
            const int mbase = p * LL + l0 + tid4;
            const float2 c0 = slow_center(kb, qb, mbase + 0);
            const float2 c1 = slow_center(kb, qb, mbase + 1);
            const float2 c2 = slow_center(kb, qb, mbase + 2);
            const float2 c3 = slow_center(kb, qb, mbase + 3);
            r1.x = wk0 * c0.y;  r2.x = c0.x * wq0;
            r1.y = wk1 * c1.y;  r2.y = c1.x * wq1;
            r1.z = wk2 * c2.y;  r2.z = c2.x * wq2;
            r1.w = wk3 * c3.y;  r2.w = c3.x * wq3;
        }

        __stcs(reinterpret_cast<float4*>(o1c + p * LL), r1);
        __stcs(reinterpret_cast<float4*>(o2c + p * LL), r2);

        rp += 4; if (rp >= 9) rp -= 9;     // m += L (L mod 9 = 4)
    }
}

extern "C" void kernel_launch(void* const* d_in, const int* in_sizes, int n_in,
                              void* d_out, int out_size) {
    const float* key   = (const float*)d_in[0];
    const float* query = (const float*)d_in[1];
    float* out1 = (float*)d_out;
    float* out2 = out1 + (size_t)256 * MM;

    depenl_v4<<<256 * 16, NT>>>(key, query, out1, out2);
}

// round 13
// speedup vs baseline: 1.0869x; 1.0869x over previous
#include <cuda_runtime.h>
#include <cstdint>

// DepenL: out1[m] = Uk[m]*Uq[mc], out2[m] = Uk[mc]*Uq[m], mc = 9*(m/9)+4.
// m = p*L + l, U[m] = x[l/128 + p/3 - 1, l%128 + p%3 - 1] (0 outside).
// L mod 9 == 4 => center = same-plane pixel l + d, d = 4 - (m mod 9) in [-4,4].
// 2-wide vectorized: each thread does 2 consecutive m (STG.64 per output),
// pair shares one center group unless r0 == 8.

#define WW   128
#define LL   16384
#define MM   147456
#define HC   16
#define NR   20        // HC + 2*2 halo rows
#define RS   136       // row stride floats
#define NT   256
#define SMN  (NR * RS)

__device__ __noinline__ float2 slow_center(const float* __restrict__ kb,
                                           const float* __restrict__ qb, int m) {
    const int g  = m / 9;
    const int mc = g * 9 + 4;
    const int pc = mc >> 14;
    const int lc = mc & 16383;
    const int ic = (pc * 11) >> 5;
    const int jc = pc - ic * 3;
    const int h  = (lc >> 7) + ic - 1;
    const int w  = (lc & 127) + jc - 1;
    if (((unsigned)h < 128u) && ((unsigned)w < 128u)) {
        const int gi = (h << 7) + w;
        return make_float2(__ldg(kb + gi), __ldg(qb + gi));
    }
    return make_float2(0.f, 0.f);
}

__global__ __launch_bounds__(NT)
void depenl_v2(const float* __restrict__ key, const float* __restrict__ query,
               float* __restrict__ out1, float* __restrict__ out2) {
    __shared__ float sK[SMN];
    __shared__ float sQ[SMN];

    const int bx    = blockIdx.x;
    const int ch    = bx >> 3;         // 0..255
    const int chunk = bx & 7;          // 0..7
    const int h0    = chunk * HC;
    const int l0    = h0 * WW;
    const int tid   = threadIdx.x;
    const int tid2  = tid * 2;

    const float* __restrict__ kb = key   + (size_t)ch * LL;
    const float* __restrict__ qb = query + (size_t)ch * LL;

    for (int idx = tid; idx < SMN; idx += NT) { sK[idx] = 0.f; sQ[idx] = 0.f; }
    __syncthreads();
    for (int t = tid; t < NR * 32; t += NT) {
        const int r = t >> 5, c4 = (t & 31) * 4;
        const int gh = h0 - 2 + r;
        if ((unsigned)gh < 128u) {
            *reinterpret_cast<float4*>(&sK[r * RS + 4 + c4]) =
                *reinterpret_cast<const float4*>(kb + gh * WW + c4);
            *reinterpret_cast<float4*>(&sQ[r * RS + 4 + c4]) =
                *reinterpret_cast<const float4*>(qb + gh * WW + c4);
        }
    }
    __syncthreads();

    float* const o1c = out1 + (size_t)ch * MM + l0 + tid2;
    float* const o2c = out2 + (size_t)ch * MM + l0 + tid2;

    int rp0 = (l0 + tid2) % 9;          // m mod 9 at p=0, it=0

    #pragma unroll
    for (int p = 0; p < 9; ++p) {
        const int i = (p * 11) >> 5;    // p/3  (constants after unroll)
        const int j = p - i * 3;        // p%3

        int r0 = rp0;
        #pragma unroll
        for (int it = 0; it < (HC * WW) / (2 * NT); ++it) {   // 4 iters
            const int l    = it * 512 + tid2;                 // local pixel, even
            const int nofs = ((l >> 7) + i + 1) * RS + (l & 127) + j + 3;

            float kn0, kn1, qn0, qn1;
            if (j == 1) {               // nofs even -> aligned float2
                const float2 k2 = *reinterpret_cast<const float2*>(&sK[nofs]);
                const float2 q2 = *reinterpret_cast<const float2*>(&sQ[nofs]);
                kn0 = k2.x; kn1 = k2.y; qn0 = q2.x; qn1 = q2.y;
            } else {
                kn0 = sK[nofs]; kn1 = sK[nofs + 1];
                qn0 = sQ[nofs]; qn1 = sQ[nofs + 1];
            }

            const int d0  = 4 - r0;
            const int lc0 = l + d0;             // group-0 center pixel (local)
            const int glc = l0 + lc0;
            float2 r1, r2;
            if ((unsigned)glc <= (unsigned)(LL - 10)) {
                const int c0  = ((lc0 >> 7) + i + 1) * RS + (lc0 & 127) + (j + 3);
                const int lc1 = lc0 + 9;
                const int c1  = ((lc1 >> 7) + i + 1) * RS + (lc1 & 127) + (j + 3);
                const float kc0 = sK[c0], qc0 = sQ[c0];
                const float kc1 = sK[c1], qc1 = sQ[c1];
                const float kB = (r0 < 8) ? kc0 : kc1;
                const float qB = (r0 < 8) ? qc0 : qc1;
                r1.x = kn0 * qc0;  r2.x = kc0 * qn0;
                r1.y = kn1 * qB;   r2.y = kB  * qn1;
            } else {
                const int mbase = p * LL + l0 + l;
                const float2 c0 = slow_center(kb, qb, mbase + 0);
                const float2 c1 = slow_center(kb, qb, mbase + 1);
                r1.x = kn0 * c0.y;  r2.x = c0.x * qn0;
                r1.y = kn1 * c1.y;  r2.y = c1.x * qn1;
            }

            __stcs(reinterpret_cast<float2*>(o1c + p * LL + it * 512), r1);
            __stcs(reinterpret_cast<float2*>(o2c + p * LL + it * 512), r2);

            r0 += 8; if (r0 >= 9) r0 -= 9;     // m += 512 (512 mod 9 = 8)
        }
        rp0 += 4; if (rp0 >= 9) rp0 -= 9;      // m += L (L mod 9 = 4)
    }
}

extern "C" void kernel_launch(void* const* d_in, const int* in_sizes, int n_in,
                              void* d_out, int out_size) {
    const float* key   = (const float*)d_in[0];
    const float* query = (const float*)d_in[1];
    float* out1 = (float*)d_out;
    float* out2 = out1 + (size_t)256 * MM;

    depenl_v2<<<256 * 8, NT>>>(key, query, out1, out2);
}